// round 8
// baseline (speedup 1.0000x reference)
#include <cuda_runtime.h>
#include <math.h>

#define N_NODES   100000
#define E_EDGES   3200000
#define FIN       512
#define F1        16
#define F2        40
#define SCAN_B    1024
#define NBLK      ((N_NODES + SCAN_B - 1) / SCAN_B)   // 98

// ---------------- packed f32x2 helpers (Blackwell) ----------------
#define PACK2(out, lo, hi) \
    asm("mov.b64 %0, {%1, %2};" : "=l"(out) : "f"(lo), "f"(hi))
#define UNPACK2(lo, hi, in) \
    asm("mov.b64 {%0, %1}, %2;" : "=f"(lo), "=f"(hi) : "l"(in))
#define FFMA2(d, a, b) \
    asm("fma.rn.f32x2 %0, %1, %2, %0;" : "+l"(d) : "l"(a), "l"(b))

// ---------------- scratch (no cudaMalloc allowed) ----------------
// Device symbols referenced ONLY from device code.
__device__ int    g_nz;                   // 0 => int64 edges, 1 => int32
__device__ int    g_cnt   [N_NODES];      // in-degree (excluding self loop)
__device__ int    g_fill  [N_NODES];      // CSR fill cursors
__device__ int    g_rowptr[N_NODES + 1];
__device__ int    g_blksum[128];
__device__ int    g_blkoff[128];
__device__ float  g_dinv  [N_NODES];
__device__ int    g_dst   [E_EDGES];
__device__ int    g_srcT  [E_EDGES];      // src staging
__device__ int    g_csrc  [E_EDGES];      // src ids grouped by dst (CSR)
__device__ float4 g_hs    [N_NODES * 4];  // layer-1 features, pre-scaled by dinv
__device__ float4 g_hs2   [N_NODES * 4];  // layer-2 features, pre-scaled by dinv
__device__ float4 g_agg   [N_NODES * 4];  // layer-2 raw aggregate

// ---------------- K0: zero counters ----------------
__global__ void k_zero(int n) {
    int i = blockIdx.x * blockDim.x + threadIdx.x;
    if (i < n) { g_cnt[i] = 0; g_fill[i] = 0; }
}

// ---------------- K0b: dtype probe (single block, self-contained) ----------------
// Sample odd 32-bit words among the first 3.2M pairs (in-bounds for both
// int32 [6.4M words] and int64 [12.8M words] interpretations).
// int64 little-endian node ids < 2^17 => odd words all zero.
__global__ void k_detect(const unsigned* __restrict__ I) {
    __shared__ int f;
    if (threadIdx.x == 0) f = 0;
    __syncthreads();
    unsigned w = I[2 * (threadIdx.x * 1001) + 1]
               | I[2 * (threadIdx.x * 4001) + 1];
    if (w != 0u) f = 1;    // benign race: any writer sets 1
    __syncthreads();
    if (threadIdx.x == 0) g_nz = f;
}

// ---------------- K1: edges -> int32 staging, histogram in-degree ----------------
__global__ void k_edge_prep(const unsigned* __restrict__ I, int E) {
    int e = blockIdx.x * blockDim.x + threadIdx.x;
    if (e >= E) return;
    int s, d;
    if (g_nz == 0) {            // int64: take low words
        s = (int)I[2 * e];
        d = (int)I[2 * (E + e)];
    } else {                    // int32
        s = (int)I[e];
        d = (int)I[E + e];
    }
    if ((unsigned)s >= (unsigned)N_NODES) s = 0;   // defensive clamp
    if ((unsigned)d >= (unsigned)N_NODES) d = 0;
    g_srcT[e] = s;
    g_dst [e] = d;
    atomicAdd(&g_cnt[d], 1);
}

// ---------------- K2a/b/c: exclusive scan of g_cnt -> g_rowptr ----------------
__global__ void k_scanA(int n) {
    __shared__ int sm[SCAN_B];
    int t = threadIdx.x;
    int i = blockIdx.x * SCAN_B + t;
    int x = (i < n) ? g_cnt[i] : 0;
    sm[t] = x;
    __syncthreads();
    for (int off = 1; off < SCAN_B; off <<= 1) {
        int v = (t >= off) ? sm[t - off] : 0;
        __syncthreads();
        sm[t] += v;
        __syncthreads();
    }
    if (i < n) g_rowptr[i] = sm[t] - x;          // exclusive, per-block partial
    if (t == SCAN_B - 1) g_blksum[blockIdx.x] = sm[t];
}
__global__ void k_scanB() {
    __shared__ int sm[128];
    int t = threadIdx.x;
    int x = (t < NBLK) ? g_blksum[t] : 0;
    sm[t] = x;
    __syncthreads();
    for (int off = 1; off < 128; off <<= 1) {
        int v = (t >= off) ? sm[t - off] : 0;
        __syncthreads();
        sm[t] += v;
        __syncthreads();
    }
    g_blkoff[t] = sm[t] - x;                     // exclusive block offsets
}
__global__ void k_scanC(int n, int E) {
    int i = blockIdx.x * blockDim.x + threadIdx.x;
    if (i < n) {
        g_rowptr[i] += g_blkoff[i >> 10];
        g_dinv[i] = rsqrtf((float)(g_cnt[i] + 1));   // +1 self loop
    }
    if (i == 0) g_rowptr[n] = E;
}

// ---------------- K3: CSR fill (scalar int atomics only) ----------------
__global__ void k_fill(int E) {
    int e = blockIdx.x * blockDim.x + threadIdx.x;
    if (e >= E) return;
    int d = g_dst[e];
    int pos = g_rowptr[d] + atomicAdd(&g_fill[d], 1);
    if ((unsigned)pos >= (unsigned)E_EDGES) pos = 0;   // defensive clamp
    g_csrc[pos] = g_srcT[e];
}

// ---------------- K4: hs = (x @ W1) * dinv[row], f32x2 inner loop ----------------
#define G_ROWS 128
#define G_KC   64
#define G_XS   68   // padded stride (floats)

__global__ __launch_bounds__(256) void k_gemm1(
    const float* __restrict__ x, const float* __restrict__ W1, int n)
{
    __shared__ float Wsm[G_KC * 16];        // 4 KB
    __shared__ float xsm[G_ROWS * G_XS];    // 34 KB
    const int tid  = threadIdx.x;
    const int row0 = blockIdx.x * G_ROWS;
    const int rg   = tid >> 2;              // 0..63 -> rows 2rg,2rg+1
    const int cg   = tid & 3;               // cols 4cg..4cg+3
    const int r0s  = (rg * 2) * G_XS;
    const int r1s  = r0s + G_XS;

    unsigned long long acc00 = 0ULL, acc01 = 0ULL;   // row0: cols (0,1),(2,3)
    unsigned long long acc10 = 0ULL, acc11 = 0ULL;   // row1

    const int f4c = tid & 15;               // x-tile loader: 16 f4 cols
    const int rof = tid >> 4;               // 16 rows per pass

    for (int kc = 0; kc < FIN; kc += G_KC) {
        __syncthreads();
        ((float4*)Wsm)[tid] = ((const float4*)W1)[kc * 4 + tid];
        #pragma unroll
        for (int p = 0; p < 8; p++) {
            int r = p * 16 + rof;
            int gr = row0 + r; if (gr >= n) gr = n - 1;   // clamp (safe re-read)
            float4 v = *(const float4*)(x + (size_t)gr * FIN + kc + f4c * 4);
            *(float4*)(xsm + r * G_XS + f4c * 4) = v;
        }
        __syncthreads();
        #pragma unroll 16
        for (int k = 0; k < G_KC; k++) {
            float4 w4 = *(const float4*)(Wsm + k * 16 + cg * 4);
            unsigned long long wp0, wp1, xp0, xp1;
            PACK2(wp0, w4.x, w4.y);
            PACK2(wp1, w4.z, w4.w);
            float x0 = xsm[r0s + k];
            float x1 = xsm[r1s + k];
            PACK2(xp0, x0, x0);
            PACK2(xp1, x1, x1);
            FFMA2(acc00, xp0, wp0);
            FFMA2(acc01, xp0, wp1);
            FFMA2(acc10, xp1, wp0);
            FFMA2(acc11, xp1, wp1);
        }
    }
    int r0 = row0 + 2 * rg;
    if (r0 < n) {
        float d = g_dinv[r0];
        float a0, a1, b0, b1;
        UNPACK2(a0, a1, acc00); UNPACK2(b0, b1, acc01);
        g_hs[(size_t)r0 * 4 + cg] = make_float4(a0 * d, a1 * d, b0 * d, b1 * d);
    }
    int r1 = r0 + 1;
    if (r1 < n) {
        float d = g_dinv[r1];
        float a0, a1, b0, b1;
        UNPACK2(a0, a1, acc10); UNPACK2(b0, b1, acc11);
        g_hs[(size_t)r1 * 4 + cg] = make_float4(a0 * d, a1 * d, b0 * d, b1 * d);
    }
}

// ---------------- K5/K6: CSR gather (atomic-free aggregation) ----------------
// Warp per node. Lane = (edge slot eq 0..7) x (feature quarter q 0..3).
// 2 edges per lane per iteration for MLP.
// phase 0: feat=g_hs,  out=g_hs2, out = relu((acc+self)*dinv + b1) * dinv
// phase 1: feat=g_hs2, out=g_agg, out = acc + self (raw; k_final scales)
__global__ __launch_bounds__(256) void k_gather(
    const float* __restrict__ b1, int phase, int n)
{
    const float4* __restrict__ feat = (phase == 0) ? g_hs  : g_hs2;
    float4*       __restrict__ outf = (phase == 0) ? g_hs2 : g_agg;

    int wid = (blockIdx.x * blockDim.x + threadIdx.x) >> 5;
    if (wid >= n) return;
    int lane = threadIdx.x & 31;
    int q  = lane & 3;
    int eq = lane >> 2;
    int start = g_rowptr[wid];
    int end   = g_rowptr[wid + 1];
    float4 acc = make_float4(0.f, 0.f, 0.f, 0.f);
    for (int e = start + eq; e < end; e += 16) {
        int e1 = e + 8;
        int s0 = g_csrc[e];
        int s1 = (e1 < end) ? g_csrc[e1] : s0;
        float4 v0 = feat[(size_t)s0 * 4 + q];
        float4 v1 = feat[(size_t)s1 * 4 + q];
        acc.x += v0.x; acc.y += v0.y; acc.z += v0.z; acc.w += v0.w;
        if (e1 < end) {
            acc.x += v1.x; acc.y += v1.y; acc.z += v1.z; acc.w += v1.w;
        }
    }
    #pragma unroll
    for (int off = 4; off < 32; off <<= 1) {
        acc.x += __shfl_xor_sync(0xffffffffu, acc.x, off);
        acc.y += __shfl_xor_sync(0xffffffffu, acc.y, off);
        acc.z += __shfl_xor_sync(0xffffffffu, acc.z, off);
        acc.w += __shfl_xor_sync(0xffffffffu, acc.w, off);
    }
    if (eq == 0) {
        float4 self = feat[(size_t)wid * 4 + q];
        acc.x += self.x; acc.y += self.y; acc.z += self.z; acc.w += self.w;
        if (phase == 0) {
            float di = g_dinv[wid];
            float4 b = ((const float4*)b1)[q];
            acc.x = fmaxf(fmaf(acc.x, di, b.x), 0.f) * di;
            acc.y = fmaxf(fmaf(acc.y, di, b.y), 0.f) * di;
            acc.z = fmaxf(fmaf(acc.z, di, b.z), 0.f) * di;
            acc.w = fmaxf(fmaf(acc.w, di, b.w), 0.f) * di;
        }
        outf[(size_t)wid * 4 + q] = acc;
    }
}

// ---------------- K7: out = log_softmax((agg*dinv) @ W2 + b2) ----------------
__global__ __launch_bounds__(128) void k_final(
    const float* __restrict__ W2, const float* __restrict__ b2,
    float* __restrict__ out, int n)
{
    __shared__ float Wsm[F1 * F2];      // 640
    __shared__ float bsm[F2];
    __shared__ float osm[128 * F2];     // 20 KB
    int tid = threadIdx.x;
    for (int i = tid; i < F1 * F2; i += 128) Wsm[i] = W2[i];
    if (tid < F2) bsm[tid] = b2[tid];
    __syncthreads();

    int row = blockIdx.x * 128 + tid;
    if (row < n) {
        float di = g_dinv[row];
        float a[F1];
        #pragma unroll
        for (int qq = 0; qq < 4; qq++) {
            float4 v = g_agg[(size_t)row * 4 + qq];
            a[qq * 4 + 0] = v.x * di; a[qq * 4 + 1] = v.y * di;
            a[qq * 4 + 2] = v.z * di; a[qq * 4 + 3] = v.w * di;
        }
        float o[F2];
        #pragma unroll
        for (int j = 0; j < F2; j++) {
            float s = bsm[j];
            #pragma unroll
            for (int k = 0; k < F1; k++) s = fmaf(a[k], Wsm[k * F2 + j], s);
            o[j] = s;
        }
        float m = o[0];
        #pragma unroll
        for (int j = 1; j < F2; j++) m = fmaxf(m, o[j]);
        float sum = 0.f;
        #pragma unroll
        for (int j = 0; j < F2; j++) sum += expf(o[j] - m);
        float lse = m + logf(sum);
        #pragma unroll
        for (int j = 0; j < F2; j++) osm[tid * F2 + j] = o[j] - lse;
    }
    __syncthreads();
    int base  = blockIdx.x * 128 * F2;
    int rows  = n - blockIdx.x * 128; if (rows > 128) rows = 128;
    int count = rows * F2;
    for (int i = tid; i < count; i += 128) out[base + i] = osm[i];
}

// ---------------- launch ----------------
extern "C" void kernel_launch(void* const* d_in, const int* in_sizes, int n_in,
                              void* d_out, int out_size) {
    // Identify inputs by element count (immune to metadata ordering):
    const float* x  = nullptr; const void* ei = nullptr;
    const float* W1 = nullptr; const float* b1 = nullptr;
    const float* W2 = nullptr; const float* b2 = nullptr;
    for (int i = 0; i < n_in; i++) {
        switch (in_sizes[i]) {
            case 51200000: x  = (const float*)d_in[i]; break;
            case 6400000:  ei = d_in[i];               break;
            case 8192:     W1 = (const float*)d_in[i]; break;
            case 16:       b1 = (const float*)d_in[i]; break;
            case 640:      W2 = (const float*)d_in[i]; break;
            case 40:       b2 = (const float*)d_in[i]; break;
            default: break;
        }
    }
    if (!x)  x  = (const float*)d_in[0];
    if (!ei) ei = d_in[1];
    if (!W1) W1 = (const float*)d_in[2];
    if (!b1) b1 = (const float*)d_in[3];
    if (!W2) W2 = (const float*)d_in[4];
    if (!b2) b2 = (const float*)d_in[5];

    const int N = N_NODES;
    const int E = E_EDGES;
    float* out = (float*)d_out;
    const unsigned* eiw = (const unsigned*)ei;

    k_zero     <<<(N + 255) / 256, 256>>>(N);
    k_detect   <<<1, 256>>>(eiw);
    k_edge_prep<<<(E + 255) / 256, 256>>>(eiw, E);
    k_scanA    <<<NBLK, SCAN_B>>>(N);
    k_scanB    <<<1, 128>>>();
    k_scanC    <<<(N + 255) / 256, 256>>>(N, E);
    k_fill     <<<(E + 255) / 256, 256>>>(E);
    k_gemm1    <<<(N + G_ROWS - 1) / G_ROWS, 256>>>(x, W1, N);
    k_gather   <<<(N * 32 + 255) / 256, 256>>>(b1, 0, N);
    k_gather   <<<(N * 32 + 255) / 256, 256>>>(b1, 1, N);
    k_final    <<<(N + 127) / 128, 128>>>(W2, b2, out, N);
}

// round 10
// speedup vs baseline: 1.6963x; 1.6963x over previous
#include <cuda_runtime.h>
#include <math.h>

#define N_NODES   100000
#define E_EDGES   3200000
#define FIN       512
#define F1        16
#define F2        40
#define SCAN_B    1024
#define NBLK      ((N_NODES + SCAN_B - 1) / SCAN_B)   // 98

// ---------------- scratch (no cudaMalloc allowed) ----------------
// Device symbols referenced ONLY from device code.
__device__ int    g_nz;                   // 0 => int64 edges, 1 => int32
__device__ int    g_cnt   [N_NODES];      // in-degree (excluding self loop)
__device__ int    g_fill  [N_NODES];      // CSR fill cursors
__device__ int    g_rowptr[N_NODES + 1];
__device__ int    g_blksum[128];
__device__ int    g_blkoff[128];
__device__ float  g_dinv  [N_NODES];
__device__ int    g_dst   [E_EDGES];
__device__ int    g_srcT  [E_EDGES];      // src staging
__device__ int    g_csrc  [E_EDGES];      // src ids grouped by dst (CSR)
__device__ float4 g_raw   [N_NODES * 4];  // x @ W1, unscaled (gemm output)
__device__ float4 g_hs    [N_NODES * 4];  // layer-1 features, pre-scaled by dinv
__device__ float4 g_hs2   [N_NODES * 4];  // layer-2 features, pre-scaled by dinv
__device__ float4 g_agg   [N_NODES * 4];  // layer-2 raw aggregate

// ---------------- K0: zero counters ----------------
__global__ void k_zero(int n) {
    int i = blockIdx.x * blockDim.x + threadIdx.x;
    if (i < n) { g_cnt[i] = 0; g_fill[i] = 0; }
}

// ---------------- K0b: dtype probe (single block, self-contained) ----------------
// int64 little-endian node ids < 2^17 => odd 32-bit words all zero.
__global__ void k_detect(const unsigned* __restrict__ I) {
    __shared__ int f;
    if (threadIdx.x == 0) f = 0;
    __syncthreads();
    unsigned w = I[2 * (threadIdx.x * 1001) + 1]
               | I[2 * (threadIdx.x * 4001) + 1];
    if (w != 0u) f = 1;    // benign race: any writer sets 1
    __syncthreads();
    if (threadIdx.x == 0) g_nz = f;
}

// ---------------- K1: edges -> int32 staging, histogram in-degree ----------------
__global__ void k_edge_prep(const unsigned* __restrict__ I, int E) {
    int e = blockIdx.x * blockDim.x + threadIdx.x;
    if (e >= E) return;
    int s, d;
    if (g_nz == 0) {            // int64: take low words
        s = (int)I[2 * e];
        d = (int)I[2 * (E + e)];
    } else {                    // int32
        s = (int)I[e];
        d = (int)I[E + e];
    }
    if ((unsigned)s >= (unsigned)N_NODES) s = 0;   // defensive clamp
    if ((unsigned)d >= (unsigned)N_NODES) d = 0;
    g_srcT[e] = s;
    g_dst [e] = d;
    atomicAdd(&g_cnt[d], 1);
}

// ---------------- K2a/b/c: exclusive scan of g_cnt -> g_rowptr ----------------
__global__ void k_scanA(int n) {
    __shared__ int sm[SCAN_B];
    int t = threadIdx.x;
    int i = blockIdx.x * SCAN_B + t;
    int x = (i < n) ? g_cnt[i] : 0;
    sm[t] = x;
    __syncthreads();
    for (int off = 1; off < SCAN_B; off <<= 1) {
        int v = (t >= off) ? sm[t - off] : 0;
        __syncthreads();
        sm[t] += v;
        __syncthreads();
    }
    if (i < n) g_rowptr[i] = sm[t] - x;          // exclusive, per-block partial
    if (t == SCAN_B - 1) g_blksum[blockIdx.x] = sm[t];
}
__global__ void k_scanB() {
    __shared__ int sm[128];
    int t = threadIdx.x;
    int x = (t < NBLK) ? g_blksum[t] : 0;
    sm[t] = x;
    __syncthreads();
    for (int off = 1; off < 128; off <<= 1) {
        int v = (t >= off) ? sm[t - off] : 0;
        __syncthreads();
        sm[t] += v;
        __syncthreads();
    }
    g_blkoff[t] = sm[t] - x;                     // exclusive block offsets
}
__global__ void k_scanC(int n, int E) {
    int i = blockIdx.x * blockDim.x + threadIdx.x;
    if (i < n) {
        g_rowptr[i] += g_blkoff[i >> 10];
        g_dinv[i] = rsqrtf((float)(g_cnt[i] + 1));   // +1 self loop
    }
    if (i == 0) g_rowptr[n] = E;
}

// ---------------- K3: CSR fill (scalar int atomics only) ----------------
__global__ void k_fill(int E) {
    int e = blockIdx.x * blockDim.x + threadIdx.x;
    if (e >= E) return;
    int d = g_dst[e];
    int pos = g_rowptr[d] + atomicAdd(&g_fill[d], 1);
    if ((unsigned)pos >= (unsigned)E_EDGES) pos = 0;   // defensive clamp
    g_csrc[pos] = g_srcT[e];
}

// ---------------- K4: raw = x @ W1 (NO dinv — runs concurrently w/ CSR build) ----------------
#define G_ROWS 128
#define G_KC   64
#define G_XS   68   // padded stride (floats)

__global__ __launch_bounds__(256) void k_gemm1(
    const float* __restrict__ x, const float* __restrict__ W1, int n)
{
    __shared__ float Wsm[G_KC * 16];        // 4 KB
    __shared__ float xsm[G_ROWS * G_XS];    // 34 KB
    const int tid  = threadIdx.x;
    const int row0 = blockIdx.x * G_ROWS;
    const int rg   = tid >> 2;              // 0..63 -> rows 2rg,2rg+1
    const int cg   = tid & 3;               // cols 4cg..4cg+3
    const int r0s  = (rg * 2) * G_XS;
    const int r1s  = r0s + G_XS;

    float4 acc0 = make_float4(0.f, 0.f, 0.f, 0.f);
    float4 acc1 = make_float4(0.f, 0.f, 0.f, 0.f);

    const int f4c = tid & 15;               // x-tile loader: 16 f4 cols
    const int rof = tid >> 4;               // 16 rows per pass

    for (int kc = 0; kc < FIN; kc += G_KC) {
        __syncthreads();
        ((float4*)Wsm)[tid] = ((const float4*)W1)[kc * 4 + tid];
        #pragma unroll
        for (int p = 0; p < 8; p++) {
            int r = p * 16 + rof;
            int gr = row0 + r; if (gr >= n) gr = n - 1;   // clamp (safe re-read)
            float4 v = *(const float4*)(x + (size_t)gr * FIN + kc + f4c * 4);
            *(float4*)(xsm + r * G_XS + f4c * 4) = v;
        }
        __syncthreads();
        #pragma unroll 16
        for (int k = 0; k < G_KC; k++) {
            float4 w4 = *(const float4*)(Wsm + k * 16 + cg * 4);
            float x0 = xsm[r0s + k];
            float x1 = xsm[r1s + k];
            acc0.x = fmaf(x0, w4.x, acc0.x);
            acc0.y = fmaf(x0, w4.y, acc0.y);
            acc0.z = fmaf(x0, w4.z, acc0.z);
            acc0.w = fmaf(x0, w4.w, acc0.w);
            acc1.x = fmaf(x1, w4.x, acc1.x);
            acc1.y = fmaf(x1, w4.y, acc1.y);
            acc1.z = fmaf(x1, w4.z, acc1.z);
            acc1.w = fmaf(x1, w4.w, acc1.w);
        }
    }
    int r0 = row0 + 2 * rg;
    if (r0 < n) g_raw[(size_t)r0 * 4 + cg] = acc0;
    int r1 = r0 + 1;
    if (r1 < n) g_raw[(size_t)r1 * 4 + cg] = acc1;
}

// ---------------- K4b: hs = raw * dinv[row] (join point) ----------------
__global__ void k_scale(int n) {
    int idx = blockIdx.x * blockDim.x + threadIdx.x;   // over n*4 quarters
    if (idx >= n * 4) return;
    float di = g_dinv[idx >> 2];
    float4 v = g_raw[idx];
    g_hs[idx] = make_float4(v.x * di, v.y * di, v.z * di, v.w * di);
}

// ---------------- K5/K6: CSR gather (atomic-free aggregation) ----------------
// Warp per node. Lane = (edge slot eq 0..7) x (feature quarter q 0..3).
// phase 0: feat=g_hs,  out=g_hs2, out = relu((acc+self)*dinv + b1) * dinv
// phase 1: feat=g_hs2, out=g_agg, out = acc + self (raw; k_final scales)
__global__ __launch_bounds__(256) void k_gather(
    const float* __restrict__ b1, int phase, int n)
{
    const float4* __restrict__ feat = (phase == 0) ? g_hs  : g_hs2;
    float4*       __restrict__ outf = (phase == 0) ? g_hs2 : g_agg;

    int wid = (blockIdx.x * blockDim.x + threadIdx.x) >> 5;
    if (wid >= n) return;
    int lane = threadIdx.x & 31;
    int q  = lane & 3;
    int eq = lane >> 2;
    int start = g_rowptr[wid];
    int end   = g_rowptr[wid + 1];
    float4 acc = make_float4(0.f, 0.f, 0.f, 0.f);
    for (int e = start + eq; e < end; e += 8) {
        int s = g_csrc[e];
        float4 v = feat[(size_t)s * 4 + q];
        acc.x += v.x; acc.y += v.y; acc.z += v.z; acc.w += v.w;
    }
    #pragma unroll
    for (int off = 4; off < 32; off <<= 1) {
        acc.x += __shfl_xor_sync(0xffffffffu, acc.x, off);
        acc.y += __shfl_xor_sync(0xffffffffu, acc.y, off);
        acc.z += __shfl_xor_sync(0xffffffffu, acc.z, off);
        acc.w += __shfl_xor_sync(0xffffffffu, acc.w, off);
    }
    if (eq == 0) {
        float4 self = feat[(size_t)wid * 4 + q];
        acc.x += self.x; acc.y += self.y; acc.z += self.z; acc.w += self.w;
        if (phase == 0) {
            float di = g_dinv[wid];
            float4 b = ((const float4*)b1)[q];
            acc.x = fmaxf(fmaf(acc.x, di, b.x), 0.f) * di;
            acc.y = fmaxf(fmaf(acc.y, di, b.y), 0.f) * di;
            acc.z = fmaxf(fmaf(acc.z, di, b.z), 0.f) * di;
            acc.w = fmaxf(fmaf(acc.w, di, b.w), 0.f) * di;
        }
        outf[(size_t)wid * 4 + q] = acc;
    }
}

// ---------------- K7: out = log_softmax((agg*dinv) @ W2 + b2) ----------------
__global__ __launch_bounds__(128) void k_final(
    const float* __restrict__ W2, const float* __restrict__ b2,
    float* __restrict__ out, int n)
{
    __shared__ float Wsm[F1 * F2];      // 640
    __shared__ float bsm[F2];
    __shared__ float osm[128 * F2];     // 20 KB
    int tid = threadIdx.x;
    for (int i = tid; i < F1 * F2; i += 128) Wsm[i] = W2[i];
    if (tid < F2) bsm[tid] = b2[tid];
    __syncthreads();

    int row = blockIdx.x * 128 + tid;
    if (row < n) {
        float di = g_dinv[row];
        float a[F1];
        #pragma unroll
        for (int qq = 0; qq < 4; qq++) {
            float4 v = g_agg[(size_t)row * 4 + qq];
            a[qq * 4 + 0] = v.x * di; a[qq * 4 + 1] = v.y * di;
            a[qq * 4 + 2] = v.z * di; a[qq * 4 + 3] = v.w * di;
        }
        float o[F2];
        #pragma unroll
        for (int j = 0; j < F2; j++) {
            float s = bsm[j];
            #pragma unroll
            for (int k = 0; k < F1; k++) s = fmaf(a[k], Wsm[k * F2 + j], s);
            o[j] = s;
        }
        float m = o[0];
        #pragma unroll
        for (int j = 1; j < F2; j++) m = fmaxf(m, o[j]);
        float sum = 0.f;
        #pragma unroll
        for (int j = 0; j < F2; j++) sum += expf(o[j] - m);
        float lse = m + logf(sum);
        #pragma unroll
        for (int j = 0; j < F2; j++) osm[tid * F2 + j] = o[j] - lse;
    }
    __syncthreads();
    int base  = blockIdx.x * 128 * F2;
    int rows  = n - blockIdx.x * 128; if (rows > 128) rows = 128;
    int count = rows * F2;
    for (int i = tid; i < count; i += 128) out[base + i] = osm[i];
}

// ---------------- launch ----------------
extern "C" void kernel_launch(void* const* d_in, const int* in_sizes, int n_in,
                              void* d_out, int out_size) {
    // Identify inputs by element count (immune to metadata ordering):
    const float* x  = nullptr; const void* ei = nullptr;
    const float* W1 = nullptr; const float* b1 = nullptr;
    const float* W2 = nullptr; const float* b2 = nullptr;
    for (int i = 0; i < n_in; i++) {
        switch (in_sizes[i]) {
            case 51200000: x  = (const float*)d_in[i]; break;
            case 6400000:  ei = d_in[i];               break;
            case 8192:     W1 = (const float*)d_in[i]; break;
            case 16:       b1 = (const float*)d_in[i]; break;
            case 640:      W2 = (const float*)d_in[i]; break;
            case 40:       b2 = (const float*)d_in[i]; break;
            default: break;
        }
    }
    if (!x)  x  = (const float*)d_in[0];
    if (!ei) ei = d_in[1];
    if (!W1) W1 = (const float*)d_in[2];
    if (!b1) b1 = (const float*)d_in[3];
    if (!W2) W2 = (const float*)d_in[4];
    if (!b2) b2 = (const float*)d_in[5];

    const int N = N_NODES;
    const int E = E_EDGES;
    float* out = (float*)d_out;
    const unsigned* eiw = (const unsigned*)ei;

    // One-time side stream + fork/join events (resources, not device memory;
    // created on first call, reused for capture; work stays deterministic).
    static cudaStream_t s1 = nullptr;
    static cudaEvent_t  evFork = nullptr, evJoin = nullptr;
    if (!s1) {
        cudaStreamCreateWithFlags(&s1, cudaStreamNonBlocking);
        cudaEventCreateWithFlags(&evFork, cudaEventDisableTiming);
        cudaEventCreateWithFlags(&evJoin, cudaEventDisableTiming);
    }

    // Fork: gemm1 (FMA-bound, no deps) overlaps the CSR build (mem/atomic-bound).
    cudaEventRecord(evFork, 0);
    cudaStreamWaitEvent(s1, evFork, 0);
    k_gemm1<<<(N + G_ROWS - 1) / G_ROWS, 256, 0, s1>>>(x, W1, N);
    cudaEventRecord(evJoin, s1);

    // CSR build chain on the main (capturing) stream.
    k_zero     <<<(N + 255) / 256, 256>>>(N);
    k_detect   <<<1, 256>>>(eiw);
    k_edge_prep<<<(E + 255) / 256, 256>>>(eiw, E);
    k_scanA    <<<NBLK, SCAN_B>>>(N);
    k_scanB    <<<1, 128>>>();
    k_scanC    <<<(N + 255) / 256, 256>>>(N, E);
    k_fill     <<<(E + 255) / 256, 256>>>(E);

    // Join: need gemm output + dinv before scaling / gathering.
    cudaStreamWaitEvent(0, evJoin, 0);
    k_scale    <<<(N * 4 + 255) / 256, 256>>>(N);
    k_gather   <<<(N * 32 + 255) / 256, 256>>>(b1, 0, N);
    k_gather   <<<(N * 32 + 255) / 256, 256>>>(b1, 1, N);
    k_final    <<<(N + 127) / 128, 128>>>(W2, b2, out, N);
}

// round 11
// speedup vs baseline: 1.7253x; 1.0171x over previous
#include <cuda_runtime.h>
#include <math.h>

#define N_NODES   100000
#define E_EDGES   3200000
#define FIN       512
#define F1        16
#define F2        40
#define SCAN_B    1024
#define NBLK      ((N_NODES + SCAN_B - 1) / SCAN_B)   // 98

// ---------------- scratch (no cudaMalloc allowed) ----------------
// Device symbols referenced ONLY from device code.
__device__ int    g_nz;                   // 0 => int64 edges, 1 => int32
__device__ int    g_done;                 // scan: blocks finished phase 1
__device__ int    g_flag;                 // scan: block offsets published
__device__ int    g_cnt   [N_NODES];      // in-degree (excluding self loop)
__device__ int    g_fill  [N_NODES];      // CSR fill cursors
__device__ int    g_rowptr[N_NODES + 1];
__device__ int    g_blksum[128];
__device__ int    g_blkoff[128];
__device__ float  g_dinv  [N_NODES];
__device__ int    g_dst   [E_EDGES];
__device__ int    g_srcT  [E_EDGES];      // src staging
__device__ int    g_csrc  [E_EDGES];      // src ids grouped by dst (CSR)
__device__ float4 g_raw   [N_NODES * 4];  // x @ W1, unscaled (gemm output)
__device__ float4 g_hs    [N_NODES * 4];  // layer-1 features, pre-scaled by dinv
__device__ float4 g_hs2   [N_NODES * 4];  // layer-2 features, pre-scaled by dinv
__device__ float4 g_agg   [N_NODES * 4];  // layer-2 raw aggregate

// ---------------- K0: zero counters + dtype probe (fused) ----------------
// Ordering vs edge_prep is at kernel boundary, so block 0 can safely do the
// probe while other blocks zero counters.
__global__ void k_zero(const unsigned* __restrict__ I, int n) {
    int i = blockIdx.x * blockDim.x + threadIdx.x;
    if (i == 0) { g_done = 0; g_flag = 0; }
    if (i < n) { g_cnt[i] = 0; g_fill[i] = 0; }
    if (blockIdx.x == 0) {
        __shared__ int f;
        if (threadIdx.x == 0) f = 0;
        __syncthreads();
        // int64 little-endian ids < 2^17 => odd 32-bit words all zero.
        unsigned w = I[2 * (threadIdx.x * 1001) + 1]
                   | I[2 * (threadIdx.x * 4001) + 1];
        if (w != 0u) f = 1;        // benign race
        __syncthreads();
        if (threadIdx.x == 0) g_nz = f;
    }
}

// ---------------- K1: edges -> int32 staging, histogram in-degree ----------------
__global__ void k_edge_prep(const unsigned* __restrict__ I, int E) {
    int e = blockIdx.x * blockDim.x + threadIdx.x;
    if (e >= E) return;
    int s, d;
    if (g_nz == 0) {            // int64: take low words
        s = (int)I[2 * e];
        d = (int)I[2 * (E + e)];
    } else {                    // int32
        s = (int)I[e];
        d = (int)I[E + e];
    }
    if ((unsigned)s >= (unsigned)N_NODES) s = 0;   // defensive clamp
    if ((unsigned)d >= (unsigned)N_NODES) d = 0;
    g_srcT[e] = s;
    g_dst [e] = d;
    atomicAdd(&g_cnt[d], 1);
}

// ---------------- K2: single-kernel exclusive scan + dinv ----------------
// 98 blocks of 1024 on 148 SMs: all blocks become resident, so a flag-based
// grid sync is deadlock-free (concurrent gemm on the side stream only delays,
// never blocks, residency). Deterministic; graph-capturable.
__global__ __launch_bounds__(SCAN_B) void k_scan(int n, int E) {
    __shared__ int sm[SCAN_B];
    __shared__ int sm2[128];
    const int t   = threadIdx.x;
    const int bid = blockIdx.x;
    const int i   = bid * SCAN_B + t;

    // Phase 1: block-local inclusive scan of counts.
    int x = (i < n) ? g_cnt[i] : 0;
    sm[t] = x;
    __syncthreads();
    for (int off = 1; off < SCAN_B; off <<= 1) {
        int v = (t >= off) ? sm[t - off] : 0;
        __syncthreads();
        sm[t] += v;
        __syncthreads();
    }
    int excl = sm[t] - x;                       // exclusive within block
    if (t == SCAN_B - 1) g_blksum[bid] = sm[t];
    __threadfence();
    if (t == SCAN_B - 1) atomicAdd(&g_done, 1);

    // Phase 2: block 0 scans the 98 block sums; others wait.
    if (bid == 0) {
        if (t == 0) {
            while (atomicAdd(&g_done, 0) < gridDim.x) __nanosleep(40);
        }
        __syncthreads();
        int y = (t < 128 && t < (int)gridDim.x) ? g_blksum[t] : 0;
        if (t < 128) sm2[t] = y;
        __syncthreads();
        for (int off = 1; off < 128; off <<= 1) {
            int v = (t >= off && t < 128) ? sm2[t - off] : 0;
            __syncthreads();
            if (t < 128) sm2[t] += v;
            __syncthreads();
        }
        if (t < 128) g_blkoff[t] = sm2[t] - y;  // exclusive block offsets
        __threadfence();
        __syncthreads();
        if (t == 0) atomicExch(&g_flag, 1);
    } else {
        if (t == 0) {
            while (atomicAdd(&g_flag, 0) == 0) __nanosleep(40);
        }
        __syncthreads();
    }

    // Phase 3: publish rowptr + dinv.
    if (i < n) {
        g_rowptr[i] = excl + g_blkoff[bid];
        g_dinv[i]   = rsqrtf((float)(x + 1));   // +1 self loop
    }
    if (bid == 0 && t == 0) g_rowptr[n] = E;
}

// ---------------- K3: CSR fill (scalar int atomics only) ----------------
__global__ void k_fill(int E) {
    int e = blockIdx.x * blockDim.x + threadIdx.x;
    if (e >= E) return;
    int d = g_dst[e];
    int pos = g_rowptr[d] + atomicAdd(&g_fill[d], 1);
    if ((unsigned)pos >= (unsigned)E_EDGES) pos = 0;   // defensive clamp
    g_csrc[pos] = g_srcT[e];
}

// ---------------- K4: raw = x @ W1 (NO dinv — overlaps the CSR build) ----------------
#define G_ROWS 128
#define G_KC   64
#define G_XS   68   // padded stride (floats)

__global__ __launch_bounds__(256) void k_gemm1(
    const float* __restrict__ x, const float* __restrict__ W1, int n)
{
    __shared__ float Wsm[G_KC * 16];        // 4 KB
    __shared__ float xsm[G_ROWS * G_XS];    // 34 KB
    const int tid  = threadIdx.x;
    const int row0 = blockIdx.x * G_ROWS;
    const int rg   = tid >> 2;              // 0..63 -> rows 2rg,2rg+1
    const int cg   = tid & 3;               // cols 4cg..4cg+3
    const int r0s  = (rg * 2) * G_XS;
    const int r1s  = r0s + G_XS;

    float4 acc0 = make_float4(0.f, 0.f, 0.f, 0.f);
    float4 acc1 = make_float4(0.f, 0.f, 0.f, 0.f);

    const int f4c = tid & 15;               // x-tile loader: 16 f4 cols
    const int rof = tid >> 4;               // 16 rows per pass

    for (int kc = 0; kc < FIN; kc += G_KC) {
        __syncthreads();
        ((float4*)Wsm)[tid] = ((const float4*)W1)[kc * 4 + tid];
        #pragma unroll
        for (int p = 0; p < 8; p++) {
            int r = p * 16 + rof;
            int gr = row0 + r; if (gr >= n) gr = n - 1;   // clamp (safe re-read)
            float4 v = *(const float4*)(x + (size_t)gr * FIN + kc + f4c * 4);
            *(float4*)(xsm + r * G_XS + f4c * 4) = v;
        }
        __syncthreads();
        #pragma unroll 16
        for (int k = 0; k < G_KC; k++) {
            float4 w4 = *(const float4*)(Wsm + k * 16 + cg * 4);
            float x0 = xsm[r0s + k];
            float x1 = xsm[r1s + k];
            acc0.x = fmaf(x0, w4.x, acc0.x);
            acc0.y = fmaf(x0, w4.y, acc0.y);
            acc0.z = fmaf(x0, w4.z, acc0.z);
            acc0.w = fmaf(x0, w4.w, acc0.w);
            acc1.x = fmaf(x1, w4.x, acc1.x);
            acc1.y = fmaf(x1, w4.y, acc1.y);
            acc1.z = fmaf(x1, w4.z, acc1.z);
            acc1.w = fmaf(x1, w4.w, acc1.w);
        }
    }
    int r0 = row0 + 2 * rg;
    if (r0 < n) g_raw[(size_t)r0 * 4 + cg] = acc0;
    int r1 = r0 + 1;
    if (r1 < n) g_raw[(size_t)r1 * 4 + cg] = acc1;
}

// ---------------- K4b: hs = raw * dinv[row] (side stream; overlaps fill) ----------------
__global__ void k_scale(int n) {
    int idx = blockIdx.x * blockDim.x + threadIdx.x;   // over n*4 quarters
    if (idx >= n * 4) return;
    float di = g_dinv[idx >> 2];
    float4 v = g_raw[idx];
    g_hs[idx] = make_float4(v.x * di, v.y * di, v.z * di, v.w * di);
}

// ---------------- K5/K6: CSR gather (atomic-free aggregation) ----------------
// Warp per node. Lane = (edge slot eq 0..7) x (feature quarter q 0..3).
// phase 0: feat=g_hs,  out=g_hs2, out = relu((acc+self)*dinv + b1) * dinv
// phase 1: feat=g_hs2, out=g_agg, out = acc + self (raw; k_final scales)
__global__ __launch_bounds__(256) void k_gather(
    const float* __restrict__ b1, int phase, int n)
{
    const float4* __restrict__ feat = (phase == 0) ? g_hs  : g_hs2;
    float4*       __restrict__ outf = (phase == 0) ? g_hs2 : g_agg;

    int wid = (blockIdx.x * blockDim.x + threadIdx.x) >> 5;
    if (wid >= n) return;
    int lane = threadIdx.x & 31;
    int q  = lane & 3;
    int eq = lane >> 2;
    int start = g_rowptr[wid];
    int end   = g_rowptr[wid + 1];
    float4 acc = make_float4(0.f, 0.f, 0.f, 0.f);
    for (int e = start + eq; e < end; e += 8) {
        int s = g_csrc[e];
        float4 v = feat[(size_t)s * 4 + q];
        acc.x += v.x; acc.y += v.y; acc.z += v.z; acc.w += v.w;
    }
    #pragma unroll
    for (int off = 4; off < 32; off <<= 1) {
        acc.x += __shfl_xor_sync(0xffffffffu, acc.x, off);
        acc.y += __shfl_xor_sync(0xffffffffu, acc.y, off);
        acc.z += __shfl_xor_sync(0xffffffffu, acc.z, off);
        acc.w += __shfl_xor_sync(0xffffffffu, acc.w, off);
    }
    if (eq == 0) {
        float4 self = feat[(size_t)wid * 4 + q];
        acc.x += self.x; acc.y += self.y; acc.z += self.z; acc.w += self.w;
        if (phase == 0) {
            float di = g_dinv[wid];
            float4 b = ((const float4*)b1)[q];
            acc.x = fmaxf(fmaf(acc.x, di, b.x), 0.f) * di;
            acc.y = fmaxf(fmaf(acc.y, di, b.y), 0.f) * di;
            acc.z = fmaxf(fmaf(acc.z, di, b.z), 0.f) * di;
            acc.w = fmaxf(fmaf(acc.w, di, b.w), 0.f) * di;
        }
        outf[(size_t)wid * 4 + q] = acc;
    }
}

// ---------------- K7: out = log_softmax((agg*dinv) @ W2 + b2) ----------------
__global__ __launch_bounds__(128) void k_final(
    const float* __restrict__ W2, const float* __restrict__ b2,
    float* __restrict__ out, int n)
{
    __shared__ float Wsm[F1 * F2];      // 640
    __shared__ float bsm[F2];
    __shared__ float osm[128 * F2];     // 20 KB
    int tid = threadIdx.x;
    for (int i = tid; i < F1 * F2; i += 128) Wsm[i] = W2[i];
    if (tid < F2) bsm[tid] = b2[tid];
    __syncthreads();

    int row = blockIdx.x * 128 + tid;
    if (row < n) {
        float di = g_dinv[row];
        float a[F1];
        #pragma unroll
        for (int qq = 0; qq < 4; qq++) {
            float4 v = g_agg[(size_t)row * 4 + qq];
            a[qq * 4 + 0] = v.x * di; a[qq * 4 + 1] = v.y * di;
            a[qq * 4 + 2] = v.z * di; a[qq * 4 + 3] = v.w * di;
        }
        float o[F2];
        #pragma unroll
        for (int j = 0; j < F2; j++) {
            float s = bsm[j];
            #pragma unroll
            for (int k = 0; k < F1; k++) s = fmaf(a[k], Wsm[k * F2 + j], s);
            o[j] = s;
        }
        float m = o[0];
        #pragma unroll
        for (int j = 1; j < F2; j++) m = fmaxf(m, o[j]);
        float sum = 0.f;
        #pragma unroll
        for (int j = 0; j < F2; j++) sum += expf(o[j] - m);
        float lse = m + logf(sum);
        #pragma unroll
        for (int j = 0; j < F2; j++) osm[tid * F2 + j] = o[j] - lse;
    }
    __syncthreads();
    int base  = blockIdx.x * 128 * F2;
    int rows  = n - blockIdx.x * 128; if (rows > 128) rows = 128;
    int count = rows * F2;
    for (int i = tid; i < count; i += 128) out[base + i] = osm[i];
}

// ---------------- launch ----------------
extern "C" void kernel_launch(void* const* d_in, const int* in_sizes, int n_in,
                              void* d_out, int out_size) {
    // Identify inputs by element count (immune to metadata ordering):
    const float* x  = nullptr; const void* ei = nullptr;
    const float* W1 = nullptr; const float* b1 = nullptr;
    const float* W2 = nullptr; const float* b2 = nullptr;
    for (int i = 0; i < n_in; i++) {
        switch (in_sizes[i]) {
            case 51200000: x  = (const float*)d_in[i]; break;
            case 6400000:  ei = d_in[i];               break;
            case 8192:     W1 = (const float*)d_in[i]; break;
            case 16:       b1 = (const float*)d_in[i]; break;
            case 640:      W2 = (const float*)d_in[i]; break;
            case 40:       b2 = (const float*)d_in[i]; break;
            default: break;
        }
    }
    if (!x)  x  = (const float*)d_in[0];
    if (!ei) ei = d_in[1];
    if (!W1) W1 = (const float*)d_in[2];
    if (!b1) b1 = (const float*)d_in[3];
    if (!W2) W2 = (const float*)d_in[4];
    if (!b2) b2 = (const float*)d_in[5];

    const int N = N_NODES;
    const int E = E_EDGES;
    float* out = (float*)d_out;
    const unsigned* eiw = (const unsigned*)ei;

    // One-time side stream + fork/join events (not device memory).
    static cudaStream_t s1 = nullptr;
    static cudaEvent_t  evFork = nullptr, evScan = nullptr, evJoin = nullptr;
    if (!s1) {
        cudaStreamCreateWithFlags(&s1, cudaStreamNonBlocking);
        cudaEventCreateWithFlags(&evFork, cudaEventDisableTiming);
        cudaEventCreateWithFlags(&evScan, cudaEventDisableTiming);
        cudaEventCreateWithFlags(&evJoin, cudaEventDisableTiming);
    }

    // Fork: gemm1 (FMA-bound) on side stream, overlapping the CSR build.
    cudaEventRecord(evFork, 0);
    cudaStreamWaitEvent(s1, evFork, 0);
    k_gemm1<<<(N + G_ROWS - 1) / G_ROWS, 256, 0, s1>>>(x, W1, N);

    // CSR build chain on the main stream.
    k_zero     <<<(N + 255) / 256, 256>>>(eiw, N);
    k_edge_prep<<<(E + 255) / 256, 256>>>(eiw, E);
    k_scan     <<<NBLK, SCAN_B>>>(N, E);
    cudaEventRecord(evScan, 0);

    // Side stream: scale = raw * dinv (needs gemm + scan), overlaps fill.
    cudaStreamWaitEvent(s1, evScan, 0);
    k_scale<<<(N * 4 + 255) / 256, 256, 0, s1>>>(N);
    cudaEventRecord(evJoin, s1);

    // Main: fill, then join and aggregate.
    k_fill     <<<(E + 255) / 256, 256>>>(E);
    cudaStreamWaitEvent(0, evJoin, 0);
    k_gather   <<<(N * 32 + 255) / 256, 256>>>(b1, 0, N);
    k_gather   <<<(N * 32 + 255) / 256, 256>>>(b1, 1, N);
    k_final    <<<(N + 127) / 128, 128>>>(W2, b2, out, N);
}